// round 15
// baseline (speedup 1.0000x reference)
#include <cuda_runtime.h>
#include <cuda_fp16.h>
#include <cstdint>
#include <cstddef>

// ---------------------------------------------------------------------------
// TernaryLinear: out[8192,4096] = x[8192,4096] @ ternarize(W[4096,4096])^T
// R15: byte-exact R5 (best, 788.54us) + K-PHASE STAGGERING: each CTA starts
// its k-chunk loop at a pseudo-random offset (wrapping mod 64). Targets the
// last invariant across all tied configs: co-resident CTAs phase-locking at
// the per-iteration cp_wait+syncthreads, idling the tensor unit ~33%.
// Evidence: tensor BUSY time is exactly the full-rate floor (452us) in both
// R11 and R13 -> the 33% gap is idle cycles, not instruction rate.
// ---------------------------------------------------------------------------

#define TOKENS 8192
#define KDIM   4096
#define NDIM   4096

__device__ __align__(16) unsigned char g_Ws8[(size_t)NDIM * KDIM]; // permuted ternary W s8 [N,K]
__device__ __align__(16) __half g_Xh[(size_t)TOKENS * KDIM];       // x fp16 [M,K]
__device__ double g_partial[2048];
__device__ float  g_absmean;

// ======================= mean(|W|) reduction ==============================

__global__ void absmean_partial_k(const float* __restrict__ w) {
    __shared__ double sred[256];
    double acc = 0.0;
    size_t base = (size_t)blockIdx.x * 8192 + threadIdx.x;
#pragma unroll 8
    for (int i = 0; i < 32; i++) acc += (double)fabsf(w[base + (size_t)i * 256]);
    sred[threadIdx.x] = acc;
    __syncthreads();
    for (int s = 128; s > 0; s >>= 1) {
        if (threadIdx.x < s) sred[threadIdx.x] += sred[threadIdx.x + s];
        __syncthreads();
    }
    if (threadIdx.x == 0) g_partial[blockIdx.x] = sred[0];
}

__global__ void absmean_final_k() {
    __shared__ double sred[256];
    double acc = 0.0;
#pragma unroll
    for (int i = 0; i < 8; i++) acc += g_partial[threadIdx.x + i * 256];
    sred[threadIdx.x] = acc;
    __syncthreads();
    for (int s = 128; s > 0; s >>= 1) {
        if (threadIdx.x < s) sred[threadIdx.x] += sred[threadIdx.x + s];
        __syncthreads();
    }
    if (threadIdx.x == 0) g_absmean = (float)(sred[0] / 16777216.0);
}

// ======================= ternarize (permuted s8) ===========================

__global__ void ternarize_k(const float* __restrict__ w) {
    const float mean = g_absmean;
    size_t idx = (size_t)blockIdx.x * blockDim.x + threadIdx.x; // 16-k block
    const float4* w4 = reinterpret_cast<const float4*>(w) + idx * 4;
    float f[16];
    float4 v0 = w4[0], v1 = w4[1], v2 = w4[2], v3 = w4[3];
    f[0]=v0.x; f[1]=v0.y; f[2]=v0.z; f[3]=v0.w;
    f[4]=v1.x; f[5]=v1.y; f[6]=v1.z; f[7]=v1.w;
    f[8]=v2.x; f[9]=v2.y; f[10]=v2.z; f[11]=v2.w;
    f[12]=v3.x; f[13]=v3.y; f[14]=v3.z; f[15]=v3.w;
    uint32_t t[16];
#pragma unroll
    for (int i = 0; i < 16; i++)
        t[i] = (fabsf(f[i]) > mean) ? ((f[i] > 0.0f) ? 0x01u : 0xFFu) : 0x00u;
    uint4 o;
    o.x = t[0] | (t[1] << 8) | (t[8]  << 16) | (t[9]  << 24);
    o.y = t[2] | (t[3] << 8) | (t[10] << 16) | (t[11] << 24);
    o.z = t[4] | (t[5] << 8) | (t[12] << 16) | (t[13] << 24);
    o.w = t[6] | (t[7] << 8) | (t[14] << 16) | (t[15] << 24);
    reinterpret_cast<uint4*>(g_Ws8)[idx] = o;
}

// ======================= x -> fp16 =========================================

__global__ void xtohalf_k(const float* __restrict__ x) {
    size_t i = (size_t)blockIdx.x * blockDim.x + threadIdx.x;
    const float4* x4 = reinterpret_cast<const float4*>(x);
    float4 v0 = x4[2 * i];
    float4 v1 = x4[2 * i + 1];
    __half2* o = reinterpret_cast<__half2*>(g_Xh);
    o[4 * i]     = __floats2half2_rn(v0.x, v0.y);
    o[4 * i + 1] = __floats2half2_rn(v0.z, v0.w);
    o[4 * i + 2] = __floats2half2_rn(v1.x, v1.y);
    o[4 * i + 3] = __floats2half2_rn(v1.z, v1.w);
}

// ======================= HMMA GEMM (R5 + k-phase stagger) ==================
// CTA 128x128, warp 32x64 (4M x 2N), K-tile 64, 3-stage cp.async, 2 CTA/SM.
// A fp16: 128B rows, 16B chunk c at r*128 + ((c ^ (r&7))<<4)
// B s8:   128B rows (64B data + 64B pad), chunk c at n*128 + ((c ^ (n&7))<<4)
// Each CTA starts at k-chunk s0 = hash(blockIdx)&63, wrapping.

static constexpr int TM = 128;
static constexpr int TN = 128;
static constexpr int TKH = 64;
static constexpr int NIT = KDIM / TKH;         // 64
static constexpr int STAGES = 3;
static constexpr int ASTAGE = TM * TKH * 2;    // 16384 (fp16)
static constexpr int BSTAGE = TN * 128;        // 16384 (s8 padded rows)
static constexpr int STAGE_BYTES = ASTAGE + BSTAGE;     // 32768
static constexpr int SMEM_BYTES = STAGES * STAGE_BYTES; // 98304

static __device__ __forceinline__ uint32_t smem_u32(const void* p) {
    uint32_t a;
    asm("{ .reg .u64 t; cvta.to.shared.u64 t, %1; cvt.u32.u64 %0, t; }"
        : "=r"(a) : "l"(p));
    return a;
}

static __device__ __forceinline__ void cp16(uint32_t dst, const void* src) {
    asm volatile("cp.async.cg.shared.global [%0], [%1], 16;"
                 :: "r"(dst), "l"((size_t)__cvta_generic_to_global(src)));
}
static __device__ __forceinline__ void cp_commit() {
    asm volatile("cp.async.commit_group;" ::: "memory");
}
template <int N>
static __device__ __forceinline__ void cp_wait() {
    asm volatile("cp.async.wait_group %0;" :: "n"(N) : "memory");
}

static __device__ __forceinline__ void ldsm4(uint32_t* r, uint32_t addr) {
    asm volatile("ldmatrix.sync.aligned.m8n8.x4.shared.b16 {%0,%1,%2,%3}, [%4];"
                 : "=r"(r[0]), "=r"(r[1]), "=r"(r[2]), "=r"(r[3])
                 : "r"(addr));
}

static __device__ __forceinline__ void mma16816(float* c, const uint32_t* a,
                                                uint32_t b0, uint32_t b1) {
    asm volatile(
        "mma.sync.aligned.m16n8k16.row.col.f32.f16.f16.f32 "
        "{%0,%1,%2,%3}, {%4,%5,%6,%7}, {%8,%9}, {%0,%1,%2,%3};"
        : "+f"(c[0]), "+f"(c[1]), "+f"(c[2]), "+f"(c[3])
        : "r"(a[0]), "r"(a[1]), "r"(a[2]), "r"(a[3]), "r"(b0), "r"(b1));
}

// ternary s8x4 -> two fp16x2 regs (bit-exact: 0x3C00 / 0x0000 / 0xBC00)
static __device__ __forceinline__ void conv8(uint32_t w, uint32_t& h01,
                                             uint32_t& h23) {
    uint32_t hb = ((w & 0x01010101u) * 0x3Cu) | (w & 0x80808080u);
    h01 = __byte_perm(hb, 0u, 0x1404);
    h23 = __byte_perm(hb, 0u, 0x3424);
}

static __device__ __forceinline__ uint32_t swz_col(int r, int c16) {
    return (uint32_t)((c16 * 16) ^ ((r & 7) << 4));
}

// ic = k-chunk index (already wrapped)
static __device__ __forceinline__ void load_chunk(int ic, int stage, int tid,
                                                  int mBase, int nBase,
                                                  uint32_t sb) {
    const uint32_t base = sb + stage * STAGE_BYTES;
    const int kofs = ic * TKH;
    // A: 1024 x 16B chunks
#pragma unroll
    for (int i = 0; i < 4; i++) {
        int u = tid + i * 256;              // 0..1023
        int r = u >> 3, c16 = u & 7;
        uint32_t dst = base + r * 128 + swz_col(r, c16);
        cp16(dst, &g_Xh[(size_t)(mBase + r) * KDIM + kofs + c16 * 8]);
    }
    // B s8: 512 x 16B chunks (128 rows x 4 chunks)
#pragma unroll
    for (int i = 0; i < 2; i++) {
        int u = tid + i * 256;              // 0..511
        int n = u >> 2, c = u & 3;
        uint32_t dst = base + ASTAGE + n * 128 + (uint32_t)(((c ^ (n & 7)) << 4));
        cp16(dst, &g_Ws8[(size_t)(nBase + n) * KDIM + kofs + c * 16]);
    }
}

__global__ void __launch_bounds__(256, 2) gemm_k(float* __restrict__ out) {
    extern __shared__ char smem[];
    const uint32_t sb = smem_u32(smem);
    const int tid = threadIdx.x, wid = tid >> 5, lid = tid & 31;
    const int warpM = wid & 3;          // 0..3
    const int warpN = wid >> 2;         // 0..1
    const int mBase = blockIdx.y * TM;
    const int nBase = blockIdx.x * TN;

    // k-phase stagger: pseudo-random start chunk per CTA
    const int s0 = (int)((blockIdx.x * 7u + blockIdx.y * 13u) & 63u);

    float c[2][8][4];
#pragma unroll
    for (int tm = 0; tm < 2; tm++)
#pragma unroll
        for (int j = 0; j < 8; j++)
#pragma unroll
            for (int q = 0; q < 4; q++) c[tm][j][q] = 0.0f;

    // prologue: fill 2 stages (chunks s0, s0+1 mod 64)
    load_chunk(s0, 0, tid, mBase, nBase, sb); cp_commit();
    load_chunk((s0 + 1) & 63, 1, tid, mBase, nBase, sb); cp_commit();

    const int lrow = lid & 15;
    const int lcol = (lid >> 4) * 16;

    // B ldmatrix row addressing: ldsm q covers n-rows q*32 + lid
    const int nA0 = warpN * 64 + lid;        // q = 0
    const int nA1 = warpN * 64 + 32 + lid;   // q = 1
    const uint32_t bRow0 = (uint32_t)(ASTAGE + nA0 * 128);
    const uint32_t bRow1 = (uint32_t)(ASTAGE + nA1 * 128);
    const uint32_t bs7 = (uint32_t)(lid & 7);

    for (int it = 0; it < NIT; it++) {
        cp_wait<STAGES - 2>();
        __syncthreads();
        if (it + STAGES - 1 < NIT)
            load_chunk((it + STAGES - 1 + s0) & 63, (it + STAGES - 1) % STAGES,
                       tid, mBase, nBase, sb);
        cp_commit();

        const uint32_t aB = sb + (it % STAGES) * STAGE_BYTES;

#pragma unroll
        for (int ks = 0; ks < 4; ks++) {
            uint32_t a[2][4];
#pragma unroll
            for (int tm = 0; tm < 2; tm++) {
                int r = warpM * 32 + tm * 16 + lrow;
                uint32_t addr = aB + r * 128 +
                    (uint32_t)((ks * 32 + lcol) ^ ((r & 7) << 4));
                ldsm4(a[tm], addr);
            }
            uint32_t bs[2][4];
            const uint32_t kc = ((uint32_t)ks ^ bs7) << 4;
            ldsm4(bs[0], aB + bRow0 + kc);
            ldsm4(bs[1], aB + bRow1 + kc);
#pragma unroll
            for (int q = 0; q < 2; q++)
#pragma unroll
                for (int j = 0; j < 4; j++) {
                    uint32_t b0, b1;
                    conv8(bs[q][j], b0, b1);
                    mma16816(c[0][q * 4 + j], a[0], b0, b1);
                    mma16816(c[1][q * 4 + j], a[1], b0, b1);
                }
        }
    }

    // Epilogue: direct fp32 stores
#pragma unroll
    for (int tm = 0; tm < 2; tm++) {
#pragma unroll
        for (int j = 0; j < 8; j++) {
            int row = mBase + warpM * 32 + tm * 16 + (lid >> 2);
            int col = nBase + warpN * 64 + j * 8 + (lid & 3) * 2;
            float2* p0 = reinterpret_cast<float2*>(out + (size_t)row * NDIM + col);
            float2* p1 = reinterpret_cast<float2*>(out + (size_t)(row + 8) * NDIM + col);
            *p0 = make_float2(c[tm][j][0], c[tm][j][1]);
            *p1 = make_float2(c[tm][j][2], c[tm][j][3]);
        }
    }
}

// ======================= launch ============================================

extern "C" void kernel_launch(void* const* d_in, const int* in_sizes, int n_in,
                              void* d_out, int out_size) {
    const float* x = (const float*)d_in[0];
    const float* w = (const float*)d_in[1];
    float* out = (float*)d_out;

    cudaFuncSetAttribute(gemm_k, cudaFuncAttributeMaxDynamicSharedMemorySize,
                         SMEM_BYTES);

    absmean_partial_k<<<2048, 256>>>(w);
    absmean_final_k<<<1, 256>>>();
    ternarize_k<<<(NDIM * KDIM / 16) / 256, 256>>>(w);
    xtohalf_k<<<(TOKENS * KDIM / 8) / 256, 256>>>(x);
    gemm_k<<<dim3(NDIM / TN, TOKENS / TM), 256, SMEM_BYTES>>>(out);
}

// round 16
// speedup vs baseline: 1.0329x; 1.0329x over previous
#include <cuda_runtime.h>
#include <cuda_fp16.h>
#include <cstdint>
#include <cstddef>

// ---------------------------------------------------------------------------
// TernaryLinear: out[8192,4096] = x[8192,4096] @ ternarize(W[4096,4096])^T
// R16 FINAL: R5 (best, 788.54us) + the single measured prep win:
// one-kernel atomic absmean (R9-vs-R12 clean A/B: -2.7us vs two-kernel).
// Everything else byte-exact R5. All other levers measured-negative:
// packed-B/4-stage (+10), K128/2-stage (+25), fused prep (+35), per-block
// re-reduce (+21), k-stagger (+22), 16-warp (+107), fp16-acc (+249),
// frag double-buffer (0), reorder/hoist (+23..+70).
// ---------------------------------------------------------------------------

#define TOKENS 8192
#define KDIM   4096
#define NDIM   4096

__device__ __align__(16) unsigned char g_Ws8[(size_t)NDIM * KDIM]; // permuted ternary W s8 [N,K]
__device__ __align__(16) __half g_Xh[(size_t)TOKENS * KDIM];       // x fp16 [M,K]
__device__ double  g_sum = 0.0;
__device__ unsigned g_cnt = 0u;
__device__ float   g_absmean;

// ======================= mean(|W|): single kernel (R9, measured best) ======

__global__ void absmean_k(const float* __restrict__ w) {
    __shared__ double sred[256];
    double acc = 0.0;
    size_t base = (size_t)blockIdx.x * 8192 + threadIdx.x;
#pragma unroll 8
    for (int i = 0; i < 32; i++) acc += (double)fabsf(w[base + (size_t)i * 256]);
    sred[threadIdx.x] = acc;
    __syncthreads();
    for (int s = 128; s > 0; s >>= 1) {
        if (threadIdx.x < s) sred[threadIdx.x] += sred[threadIdx.x + s];
        __syncthreads();
    }
    if (threadIdx.x == 0) {
        atomicAdd(&g_sum, sred[0]);
        __threadfence();
        unsigned t = atomicAdd(&g_cnt, 1u);
        if (t == gridDim.x - 1) {        // last block finalizes + resets
            g_absmean = (float)(g_sum / 16777216.0);
            g_sum = 0.0;
            g_cnt = 0u;
        }
    }
}

// ======================= ternarize (permuted s8, R5) =======================
// One thread per 16-k block. Byte pos 4c+{0,1,2,3} = tern(k = 2c,2c+1,2c+8,2c+9),
// c = 0..3, so ldmatrix + conv8 yields m16n8k16 B fragments directly.

__global__ void ternarize_k(const float* __restrict__ w) {
    const float mean = g_absmean;
    size_t idx = (size_t)blockIdx.x * blockDim.x + threadIdx.x; // 16-k block
    const float4* w4 = reinterpret_cast<const float4*>(w) + idx * 4;
    float f[16];
    float4 v0 = w4[0], v1 = w4[1], v2 = w4[2], v3 = w4[3];
    f[0]=v0.x; f[1]=v0.y; f[2]=v0.z; f[3]=v0.w;
    f[4]=v1.x; f[5]=v1.y; f[6]=v1.z; f[7]=v1.w;
    f[8]=v2.x; f[9]=v2.y; f[10]=v2.z; f[11]=v2.w;
    f[12]=v3.x; f[13]=v3.y; f[14]=v3.z; f[15]=v3.w;
    uint32_t t[16];
#pragma unroll
    for (int i = 0; i < 16; i++)
        t[i] = (fabsf(f[i]) > mean) ? ((f[i] > 0.0f) ? 0x01u : 0xFFu) : 0x00u;
    uint4 o;
    o.x = t[0] | (t[1] << 8) | (t[8]  << 16) | (t[9]  << 24);
    o.y = t[2] | (t[3] << 8) | (t[10] << 16) | (t[11] << 24);
    o.z = t[4] | (t[5] << 8) | (t[12] << 16) | (t[13] << 24);
    o.w = t[6] | (t[7] << 8) | (t[14] << 16) | (t[15] << 24);
    reinterpret_cast<uint4*>(g_Ws8)[idx] = o;
}

// ======================= x -> fp16 (R5) ====================================

__global__ void xtohalf_k(const float* __restrict__ x) {
    size_t i = (size_t)blockIdx.x * blockDim.x + threadIdx.x;
    const float4* x4 = reinterpret_cast<const float4*>(x);
    float4 v0 = x4[2 * i];
    float4 v1 = x4[2 * i + 1];
    __half2* o = reinterpret_cast<__half2*>(g_Xh);
    o[4 * i]     = __floats2half2_rn(v0.x, v0.y);
    o[4 * i + 1] = __floats2half2_rn(v0.z, v0.w);
    o[4 * i + 2] = __floats2half2_rn(v1.x, v1.y);
    o[4 * i + 3] = __floats2half2_rn(v1.z, v1.w);
}

// ======================= HMMA GEMM (R5, byte-exact) ========================
// CTA 128x128, warp 32x64 (4M x 2N), K-tile 64, 3-stage cp.async, 2 CTA/SM.
// A fp16: 128B rows, 16B chunk c at r*128 + ((c ^ (r&7))<<4)
// B s8:   128B rows (64B data + 64B pad), chunk c at n*128 + ((c ^ (n&7))<<4)

static constexpr int TM = 128;
static constexpr int TN = 128;
static constexpr int TKH = 64;
static constexpr int NIT = KDIM / TKH;         // 64
static constexpr int STAGES = 3;
static constexpr int ASTAGE = TM * TKH * 2;    // 16384 (fp16)
static constexpr int BSTAGE = TN * 128;        // 16384 (s8 padded rows)
static constexpr int STAGE_BYTES = ASTAGE + BSTAGE;     // 32768
static constexpr int SMEM_BYTES = STAGES * STAGE_BYTES; // 98304

static __device__ __forceinline__ uint32_t smem_u32(const void* p) {
    uint32_t a;
    asm("{ .reg .u64 t; cvta.to.shared.u64 t, %1; cvt.u32.u64 %0, t; }"
        : "=r"(a) : "l"(p));
    return a;
}

static __device__ __forceinline__ void cp16(uint32_t dst, const void* src) {
    asm volatile("cp.async.cg.shared.global [%0], [%1], 16;"
                 :: "r"(dst), "l"((size_t)__cvta_generic_to_global(src)));
}
static __device__ __forceinline__ void cp_commit() {
    asm volatile("cp.async.commit_group;" ::: "memory");
}
template <int N>
static __device__ __forceinline__ void cp_wait() {
    asm volatile("cp.async.wait_group %0;" :: "n"(N) : "memory");
}

static __device__ __forceinline__ void ldsm4(uint32_t* r, uint32_t addr) {
    asm volatile("ldmatrix.sync.aligned.m8n8.x4.shared.b16 {%0,%1,%2,%3}, [%4];"
                 : "=r"(r[0]), "=r"(r[1]), "=r"(r[2]), "=r"(r[3])
                 : "r"(addr));
}

static __device__ __forceinline__ void mma16816(float* c, const uint32_t* a,
                                                uint32_t b0, uint32_t b1) {
    asm volatile(
        "mma.sync.aligned.m16n8k16.row.col.f32.f16.f16.f32 "
        "{%0,%1,%2,%3}, {%4,%5,%6,%7}, {%8,%9}, {%0,%1,%2,%3};"
        : "+f"(c[0]), "+f"(c[1]), "+f"(c[2]), "+f"(c[3])
        : "r"(a[0]), "r"(a[1]), "r"(a[2]), "r"(a[3]), "r"(b0), "r"(b1));
}

// ternary s8x4 -> two fp16x2 regs (bit-exact: 0x3C00 / 0x0000 / 0xBC00)
static __device__ __forceinline__ void conv8(uint32_t w, uint32_t& h01,
                                             uint32_t& h23) {
    uint32_t hb = ((w & 0x01010101u) * 0x3Cu) | (w & 0x80808080u);
    h01 = __byte_perm(hb, 0u, 0x1404);
    h23 = __byte_perm(hb, 0u, 0x3424);
}

static __device__ __forceinline__ uint32_t swz_col(int r, int c16) {
    return (uint32_t)((c16 * 16) ^ ((r & 7) << 4));
}

static __device__ __forceinline__ void load_chunk(int it, int stage, int tid,
                                                  int mBase, int nBase,
                                                  uint32_t sb) {
    const uint32_t base = sb + stage * STAGE_BYTES;
    const int kofs = it * TKH;
    // A: 1024 x 16B chunks
#pragma unroll
    for (int i = 0; i < 4; i++) {
        int u = tid + i * 256;              // 0..1023
        int r = u >> 3, c16 = u & 7;
        uint32_t dst = base + r * 128 + swz_col(r, c16);
        cp16(dst, &g_Xh[(size_t)(mBase + r) * KDIM + kofs + c16 * 8]);
    }
    // B s8: 512 x 16B chunks (128 rows x 4 chunks)
#pragma unroll
    for (int i = 0; i < 2; i++) {
        int u = tid + i * 256;              // 0..511
        int n = u >> 2, c = u & 3;
        uint32_t dst = base + ASTAGE + n * 128 + (uint32_t)(((c ^ (n & 7)) << 4));
        cp16(dst, &g_Ws8[(size_t)(nBase + n) * KDIM + kofs + c * 16]);
    }
}

__global__ void __launch_bounds__(256, 2) gemm_k(float* __restrict__ out) {
    extern __shared__ char smem[];
    const uint32_t sb = smem_u32(smem);
    const int tid = threadIdx.x, wid = tid >> 5, lid = tid & 31;
    const int warpM = wid & 3;          // 0..3
    const int warpN = wid >> 2;         // 0..1
    const int mBase = blockIdx.y * TM;
    const int nBase = blockIdx.x * TN;

    float c[2][8][4];
#pragma unroll
    for (int tm = 0; tm < 2; tm++)
#pragma unroll
        for (int j = 0; j < 8; j++)
#pragma unroll
            for (int q = 0; q < 4; q++) c[tm][j][q] = 0.0f;

    // prologue: fill 2 stages
    load_chunk(0, 0, tid, mBase, nBase, sb); cp_commit();
    load_chunk(1, 1, tid, mBase, nBase, sb); cp_commit();

    const int lrow = lid & 15;
    const int lcol = (lid >> 4) * 16;

    // B ldmatrix row addressing: ldsm q covers n-rows q*32 + lid
    const int nA0 = warpN * 64 + lid;        // q = 0
    const int nA1 = warpN * 64 + 32 + lid;   // q = 1
    const uint32_t bRow0 = (uint32_t)(ASTAGE + nA0 * 128);
    const uint32_t bRow1 = (uint32_t)(ASTAGE + nA1 * 128);
    const uint32_t bs7 = (uint32_t)(lid & 7);

    for (int it = 0; it < NIT; it++) {
        cp_wait<STAGES - 2>();
        __syncthreads();
        if (it + STAGES - 1 < NIT)
            load_chunk(it + STAGES - 1, (it + STAGES - 1) % STAGES, tid,
                       mBase, nBase, sb);
        cp_commit();

        const uint32_t aB = sb + (it % STAGES) * STAGE_BYTES;

#pragma unroll
        for (int ks = 0; ks < 4; ks++) {
            uint32_t a[2][4];
#pragma unroll
            for (int tm = 0; tm < 2; tm++) {
                int r = warpM * 32 + tm * 16 + lrow;
                uint32_t addr = aB + r * 128 +
                    (uint32_t)((ks * 32 + lcol) ^ ((r & 7) << 4));
                ldsm4(a[tm], addr);
            }
            uint32_t bs[2][4];
            const uint32_t kc = ((uint32_t)ks ^ bs7) << 4;
            ldsm4(bs[0], aB + bRow0 + kc);
            ldsm4(bs[1], aB + bRow1 + kc);
#pragma unroll
            for (int q = 0; q < 2; q++)
#pragma unroll
                for (int j = 0; j < 4; j++) {
                    uint32_t b0, b1;
                    conv8(bs[q][j], b0, b1);
                    mma16816(c[0][q * 4 + j], a[0], b0, b1);
                    mma16816(c[1][q * 4 + j], a[1], b0, b1);
                }
        }
    }

    // Epilogue: direct fp32 stores
#pragma unroll
    for (int tm = 0; tm < 2; tm++) {
#pragma unroll
        for (int j = 0; j < 8; j++) {
            int row = mBase + warpM * 32 + tm * 16 + (lid >> 2);
            int col = nBase + warpN * 64 + j * 8 + (lid & 3) * 2;
            float2* p0 = reinterpret_cast<float2*>(out + (size_t)row * NDIM + col);
            float2* p1 = reinterpret_cast<float2*>(out + (size_t)(row + 8) * NDIM + col);
            *p0 = make_float2(c[tm][j][0], c[tm][j][1]);
            *p1 = make_float2(c[tm][j][2], c[tm][j][3]);
        }
    }
}

// ======================= launch ============================================

extern "C" void kernel_launch(void* const* d_in, const int* in_sizes, int n_in,
                              void* d_out, int out_size) {
    const float* x = (const float*)d_in[0];
    const float* w = (const float*)d_in[1];
    float* out = (float*)d_out;

    cudaFuncSetAttribute(gemm_k, cudaFuncAttributeMaxDynamicSharedMemorySize,
                         SMEM_BYTES);

    absmean_k<<<2048, 256>>>(w);
    ternarize_k<<<(NDIM * KDIM / 16) / 256, 256>>>(w);
    xtohalf_k<<<(TOKENS * KDIM / 8) / 256, 256>>>(x);
    gemm_k<<<dim3(NDIM / TN, TOKENS / TM), 256, SMEM_BYTES>>>(out);
}